// round 16
// baseline (speedup 1.0000x reference)
#include <cuda_runtime.h>
#include <cuda_fp16.h>
#include <cstdint>

#define NB 4
#define CG 9
#define DD 16
#define DCELLS (DD*DD*DD)       // 4096 cells
#define HWSZ (1024*1024)
#define TABLE_BYTES (DCELLS * 32)   // 128 KB

// Packed projected grid, 32B per entry (r,g,b):
//   lo.x=(c0(g,b),c1(g,b)) lo.y=(c2(g,b),c0(g,b+1)) lo.z=(c1(g,b+1),c2(g,b+1))
//   lo.w=(c0(g+1,b),c1(g+1,b)) hi.x=(c2(g+1,b),c0(g+1,b+1)) hi.y=(c1(g+1,b+1),c2(g+1,b+1))
// Entries with g==15 or b==15 are never read (ig,ib <= 14). 512 KB scratch.
__device__ uint4 d_pgrid[NB * DCELLS * 2];

// ---------------------------------------------------------------------------
// Kernel 1: one block per (n, r)-slab. Project 256 cells (g,b) through
// conv_w[:, :9] into smem, then pack 4-corner 32B entries.
// ---------------------------------------------------------------------------
__global__ __launch_bounds__(256) void project_grid_kernel(
    const float* __restrict__ grid, const float* __restrict__ cw)
{
    __shared__ float sp[256][3];
    const int n = blockIdx.x >> 4;          // image
    const int r = blockIdx.x & 15;          // r-slab
    const int t = threadIdx.x;              // g*16 + b
    const int cell = r * 256 + t;

    const float* g0 = grid + (size_t)n * CG * DCELLS + cell;
    float a0 = 0.f, a1 = 0.f, a2 = 0.f;
#pragma unroll
    for (int c = 0; c < CG; c++) {
        float v = g0[c * DCELLS];
        a0 = fmaf(cw[0 * 12 + c], v, a0);
        a1 = fmaf(cw[1 * 12 + c], v, a1);
        a2 = fmaf(cw[2 * 12 + c], v, a2);
    }
    sp[t][0] = a0; sp[t][1] = a1; sp[t][2] = a2;
    __syncthreads();

    const int g = t >> 4, b = t & 15;
    const int tb  = (b < 15) ? t + 1 : t;            // (g, b+1)
    const int tg  = (g < 15) ? t + 16 : t;           // (g+1, b)
    const int tgb = (b < 15) ? tg + 1 : tg;          // (g+1, b+1)

    __half2 l0 = __floats2half2_rn(sp[t  ][0], sp[t  ][1]);
    __half2 l1 = __floats2half2_rn(sp[t  ][2], sp[tb ][0]);
    __half2 l2 = __floats2half2_rn(sp[tb ][1], sp[tb ][2]);
    __half2 l3 = __floats2half2_rn(sp[tg ][0], sp[tg ][1]);
    __half2 h0 = __floats2half2_rn(sp[tg ][2], sp[tgb][0]);
    __half2 h1 = __floats2half2_rn(sp[tgb][1], sp[tgb][2]);

    uint4 lo, hi;
    lo.x = *(const unsigned int*)&l0;
    lo.y = *(const unsigned int*)&l1;
    lo.z = *(const unsigned int*)&l2;
    lo.w = *(const unsigned int*)&l3;
    hi.x = *(const unsigned int*)&h0;
    hi.y = *(const unsigned int*)&h1;
    hi.z = 0u; hi.w = 0u;

    uint4* dst = d_pgrid + (((size_t)(n << 12) + cell) << 1);
    dst[0] = lo;
    dst[1] = hi;
}

// ---------------------------------------------------------------------------
// Kernel 2: fused slice + conv. 128KB 4-corner table bulk-copied into smem;
// per pixel: 2 x (LDS.128 + LDS.64). 1024 threads, 1 CTA/SM (32 warps, 64 regs).
// ---------------------------------------------------------------------------
struct F3 { float x, y, z; };

__device__ __forceinline__ uint32_t smem_u32(const void* p) {
    uint32_t a;
    asm("{ .reg .u64 t; cvta.to.shared.u64 t, %1; cvt.u32.u64 %0, t; }"
        : "=r"(a) : "l"(p));
    return a;
}

// Unpack one b-pair triple (3 half2 words) and lerp along b.
__device__ __forceinline__ F3 unpack_lerp_b3(unsigned int w0, unsigned int w1,
                                             unsigned int w2, float fb) {
    float2 p0 = __half22float2(*(const __half2*)&w0);   // c0(b), c1(b)
    float2 p1 = __half22float2(*(const __half2*)&w1);   // c2(b), c0(b+1)
    float2 p2 = __half22float2(*(const __half2*)&w2);   // c1(b+1), c2(b+1)
    F3 r;
    r.x = fmaf(fb, p1.y - p0.x, p0.x);
    r.y = fmaf(fb, p2.x - p0.y, p0.y);
    r.z = fmaf(fb, p2.y - p1.x, p1.x);
    return r;
}

__device__ __forceinline__ F3 lerp3(F3 a, F3 b, float t) {
    F3 r;
    r.x = fmaf(t, b.x - a.x, a.x);
    r.y = fmaf(t, b.y - a.y, a.y);
    r.z = fmaf(t, b.z - a.z, a.z);
    return r;
}

__global__ __launch_bounds__(1024, 1) void slice_conv_kernel(
    const float* __restrict__ guide,
    const float* __restrict__ cw,
    const float* __restrict__ cb,
    float* __restrict__ out)
{
    extern __shared__ uint4 sg[];            // 8192 * 16B = 128 KB
    __shared__ alignas(8) uint64_t mbar;
    const int n = blockIdx.y;

    const float4* gR = (const float4*)(guide + (size_t)(n * 3 + 0) * HWSZ);
    const float4* gG = (const float4*)(guide + (size_t)(n * 3 + 1) * HWSZ);
    const float4* gB = (const float4*)(guide + (size_t)(n * 3 + 2) * HWSZ);
    float4* oR = (float4*)(out + (size_t)(n * 3 + 0) * HWSZ);
    float4* oG = (float4*)(out + (size_t)(n * 3 + 1) * HWSZ);
    float4* oB = (float4*)(out + (size_t)(n * 3 + 2) * HWSZ);

    const int nq     = HWSZ / 4;
    const int stride = gridDim.x * blockDim.x;
    int q = blockIdx.x * blockDim.x + threadIdx.x;

    // Prime the guide pipeline (DRAM latency overlaps the bulk copy).
    float4 r4, g4, b4;
    bool live = (q < nq);
    if (live) {
        r4 = __ldcs(gR + q);
        g4 = __ldcs(gG + q);
        b4 = __ldcs(gB + q);
    }

    // Bulk-async stage the 128KB table.
    uint32_t mb = smem_u32(&mbar);
    if (threadIdx.x == 0) {
        asm volatile("mbarrier.init.shared.b64 [%0], %1;" :: "r"(mb), "r"(1) : "memory");
    }
    __syncthreads();
    if (threadIdx.x == 0) {
        uint32_t dst = smem_u32(sg);
        const void* src = (const void*)(d_pgrid + ((size_t)n << 13));
        asm volatile("mbarrier.arrive.expect_tx.shared.b64 _, [%0], %1;"
                     :: "r"(mb), "r"((uint32_t)TABLE_BYTES) : "memory");
        asm volatile("cp.async.bulk.shared::cluster.global.mbarrier::complete_tx::bytes "
                     "[%0], [%1], %2, [%3];"
                     :: "r"(dst), "l"(src), "r"((uint32_t)TABLE_BYTES), "r"(mb)
                     : "memory");
    }
    {
        uint32_t done = 0;
        while (!done) {
            asm volatile(
                "{\n\t.reg .pred p;\n\t"
                "mbarrier.try_wait.parity.acquire.cta.shared::cta.b64 p, [%1], %2, 0x989680;\n\t"
                "selp.b32 %0, 1, 0, p;\n\t}"
                : "=r"(done) : "r"(mb), "r"(0u) : "memory");
        }
    }

    if (!live) return;

    const uint2* sg2 = (const uint2*)sg;

    const float wr9 = cw[ 9], wr10 = cw[10], wr11 = cw[11], br = cb[0];
    const float wg9 = cw[21], wg10 = cw[22], wg11 = cw[23], bg = cb[1];
    const float wb9 = cw[33], wb10 = cw[34], wb11 = cw[35], bb = cb[2];

    while (q < nq) {
        int qn = q + stride;
        float4 rn, gn, bn;
        if (qn < nq) {
            rn = __ldcs(gR + qn);
            gn = __ldcs(gG + qn);
            bn = __ldcs(gB + qn);
        }

        float4 or4, og4, ob4;
        const float* rr = (const float*)&r4;
        const float* gg = (const float*)&g4;
        const float* bv = (const float*)&b4;
        float* po0 = (float*)&or4;
        float* po1 = (float*)&og4;
        float* po2 = (float*)&ob4;

#pragma unroll
        for (int e = 0; e < 4; e++) {
            float r = rr[e], g = gg[e], b = bv[e];

            float crd = __saturatef(r) * 15.f;
            float cgd = __saturatef(g) * 15.f;
            float cbd = __saturatef(b) * 15.f;
            int ir = (int)crd; ir = ir > 14 ? 14 : ir;
            int ig = (int)cgd; ig = ig > 14 ? 14 : ig;
            int ib = (int)cbd; ib = ib > 14 ? 14 : ib;
            float fr = crd - (float)ir;
            float fg = cgd - (float)ig;
            float fb = cbd - (float)ib;

            int base = ir * 256 + ig * 16 + ib;   // entry index

            // Corner block (ir): LDS.128 + LDS.64
            uint4 lo0 = sg [2 * base];
            uint2 hi0 = sg2[4 * base + 2];
            // Corner block (ir+1): entry +256
            uint4 lo1 = sg [2 * base + 512];
            uint2 hi1 = sg2[4 * base + 1026];

            F3 c00 = unpack_lerp_b3(lo0.x, lo0.y, lo0.z, fb);   // (ir, ig)
            F3 c01 = unpack_lerp_b3(lo0.w, hi0.x, hi0.y, fb);   // (ir, ig+1)
            F3 c10 = unpack_lerp_b3(lo1.x, lo1.y, lo1.z, fb);   // (ir+1, ig)
            F3 c11 = unpack_lerp_b3(lo1.w, hi1.x, hi1.y, fb);   // (ir+1, ig+1)
            F3 c0  = lerp3(c00, c01, fg);
            F3 c1  = lerp3(c10, c11, fg);
            F3 cc  = lerp3(c0, c1, fr);

            po0[e] = fmaf(wr11, b, fmaf(wr10, g, fmaf(wr9, r, cc.x + br)));
            po1[e] = fmaf(wg11, b, fmaf(wg10, g, fmaf(wg9, r, cc.y + bg)));
            po2[e] = fmaf(wb11, b, fmaf(wb10, g, fmaf(wb9, r, cc.z + bb)));
        }

        __stcs(oR + q, or4);
        __stcs(oG + q, og4);
        __stcs(oB + q, ob4);

        q = qn;
        r4 = rn; g4 = gn; b4 = bn;
    }
}

// ---------------------------------------------------------------------------
// Launch
// ---------------------------------------------------------------------------
extern "C" void kernel_launch(void* const* d_in, const int* in_sizes, int n_in,
                              void* d_out, int out_size) {
    const float* grid  = (const float*)d_in[0];   // (4,9,16,16,16)
    const float* guide = (const float*)d_in[1];   // (4,3,1024,1024)
    const float* cw    = (const float*)d_in[2];   // (3,12)
    const float* cb    = (const float*)d_in[3];   // (3,)
    float* out = (float*)d_out;                   // (4,3,1024,1024)

    cudaFuncSetAttribute(slice_conv_kernel,
                         cudaFuncAttributeMaxDynamicSharedMemorySize, TABLE_BYTES);

    project_grid_kernel<<<NB * DD, 256>>>(grid, cw);

    dim3 blocks(37, NB);   // 148 CTAs = 148 SMs x 1 CTA (128KB smem each)
    slice_conv_kernel<<<blocks, 1024, TABLE_BYTES>>>(guide, cw, cb, out);
}

// round 17
// speedup vs baseline: 1.2189x; 1.2189x over previous
#include <cuda_runtime.h>
#include <cuda_fp16.h>
#include <cstdint>

#define NB 4
#define CG 9
#define DD 16
#define DCELLS (DD*DD*DD)       // 4096 cells
#define HWSZ (1024*1024)
#define TABLE_BYTES (DCELLS * 16)   // 64 KB

// Packed projected grid, 16B per entry (r,g,b), channel-aligned half2 lanes:
//   x=(c0(b),c1(b))  y=(c2(b),0)  z=(c0(b+1),c1(b+1))  w=(c2(b+1),0)
// so the b-lerp is elementwise half2 math. 4 * 4096 * 16B = 256KB scratch.
__device__ uint4 d_pgrid[NB * DCELLS];

// ---------------------------------------------------------------------------
// Kernel 1: project 9-channel grid through conv_w[:, :9] -> packed half2 pairs.
// Coalesced: thread == cell; b+1 neighbor via shfl (lanes 15/31 hold b=15
// cells whose hi-halves are never read, since ib <= 14).
// ---------------------------------------------------------------------------
__global__ void project_grid_kernel(const float* __restrict__ grid,
                                    const float* __restrict__ cw) {
    int idx = blockIdx.x * blockDim.x + threadIdx.x;
    if (idx >= NB * DCELLS) return;
    int n    = idx >> 12;       // / 4096
    int cell = idx & 4095;      // r*256 + g*16 + b

    const float* g0 = grid + (size_t)n * CG * DCELLS + cell;

    float a0 = 0.f, a1 = 0.f, a2 = 0.f;
#pragma unroll
    for (int c = 0; c < CG; c++) {
        float v = g0[c * DCELLS];
        a0 = fmaf(cw[0 * 12 + c], v, a0);
        a1 = fmaf(cw[1 * 12 + c], v, a1);
        a2 = fmaf(cw[2 * 12 + c], v, a2);
    }

    float h0 = __shfl_down_sync(0xFFFFFFFFu, a0, 1);
    float h1 = __shfl_down_sync(0xFFFFFFFFu, a1, 1);
    float h2 = __shfl_down_sync(0xFFFFFFFFu, a2, 1);

    __half2 lo01 = __floats2half2_rn(a0, a1);   // (c0(b),   c1(b))
    __half2 lo2  = __floats2half2_rn(a2, 0.f);  // (c2(b),   0)
    __half2 hi01 = __floats2half2_rn(h0, h1);   // (c0(b+1), c1(b+1))
    __half2 hi2  = __floats2half2_rn(h2, 0.f);  // (c2(b+1), 0)

    uint4 e;
    e.x = *(const unsigned int*)&lo01;
    e.y = *(const unsigned int*)&lo2;
    e.z = *(const unsigned int*)&hi01;
    e.w = *(const unsigned int*)&hi2;
    d_pgrid[idx] = e;
}

// ---------------------------------------------------------------------------
// Kernel 2: fused slice + conv. 64KB table bulk-copied to smem; 4x LDS.128
// per pixel; trilinear lerp entirely in HFMA2/HSUB2; 512 threads, 2 CTAs/SM.
// ---------------------------------------------------------------------------
struct H2P { __half2 a, c; };   // (c0,c1) and (c2,·)

__device__ __forceinline__ uint32_t smem_u32(const void* p) {
    uint32_t a;
    asm("{ .reg .u64 t; cvta.to.shared.u64 t, %1; cvt.u32.u64 %0, t; }"
        : "=r"(a) : "l"(p));
    return a;
}

// b-lerp an entry: lo + fb*(hi - lo), elementwise on channel-aligned half2.
__device__ __forceinline__ H2P lerp_b(uint4 e, __half2 fb2) {
    __half2 lo01 = *(const __half2*)&e.x;
    __half2 lo2  = *(const __half2*)&e.y;
    __half2 hi01 = *(const __half2*)&e.z;
    __half2 hi2  = *(const __half2*)&e.w;
    H2P r;
    r.a = __hfma2(fb2, __hsub2(hi01, lo01), lo01);
    r.c = __hfma2(fb2, __hsub2(hi2,  lo2),  lo2);
    return r;
}

__device__ __forceinline__ H2P lerp_p(H2P a, H2P b, __half2 t2) {
    H2P r;
    r.a = __hfma2(t2, __hsub2(b.a, a.a), a.a);
    r.c = __hfma2(t2, __hsub2(b.c, a.c), a.c);
    return r;
}

__global__ __launch_bounds__(512, 2) void slice_conv_kernel(
    const float* __restrict__ guide,
    const float* __restrict__ cw,
    const float* __restrict__ cb,
    float* __restrict__ out)
{
    extern __shared__ uint4 sg[];            // 4096 * 16B = 64 KB
    __shared__ alignas(8) uint64_t mbar;
    const int n = blockIdx.y;

    const float4* gR = (const float4*)(guide + (size_t)(n * 3 + 0) * HWSZ);
    const float4* gG = (const float4*)(guide + (size_t)(n * 3 + 1) * HWSZ);
    const float4* gB = (const float4*)(guide + (size_t)(n * 3 + 2) * HWSZ);
    float4* oR = (float4*)(out + (size_t)(n * 3 + 0) * HWSZ);
    float4* oG = (float4*)(out + (size_t)(n * 3 + 1) * HWSZ);
    float4* oB = (float4*)(out + (size_t)(n * 3 + 2) * HWSZ);

    const int nq     = HWSZ / 4;
    const int stride = gridDim.x * blockDim.x;
    int q = blockIdx.x * blockDim.x + threadIdx.x;

    // Prime the guide pipeline first (DRAM latency overlaps the bulk copy).
    float4 r4, g4, b4;
    bool live = (q < nq);
    if (live) {
        r4 = __ldcs(gR + q);
        g4 = __ldcs(gG + q);
        b4 = __ldcs(gB + q);
    }

    // Bulk-async stage the 64KB table.
    uint32_t mb = smem_u32(&mbar);
    if (threadIdx.x == 0) {
        asm volatile("mbarrier.init.shared.b64 [%0], %1;" :: "r"(mb), "r"(1) : "memory");
    }
    __syncthreads();
    if (threadIdx.x == 0) {
        uint32_t dst = smem_u32(sg);
        const void* src = (const void*)(d_pgrid + n * DCELLS);
        asm volatile("mbarrier.arrive.expect_tx.shared.b64 _, [%0], %1;"
                     :: "r"(mb), "r"((uint32_t)TABLE_BYTES) : "memory");
        asm volatile("cp.async.bulk.shared::cluster.global.mbarrier::complete_tx::bytes "
                     "[%0], [%1], %2, [%3];"
                     :: "r"(dst), "l"(src), "r"((uint32_t)TABLE_BYTES), "r"(mb)
                     : "memory");
    }
    // All threads wait for the copy (acquire orders subsequent LDS).
    {
        uint32_t done = 0;
        while (!done) {
            asm volatile(
                "{\n\t.reg .pred p;\n\t"
                "mbarrier.try_wait.parity.acquire.cta.shared::cta.b64 p, [%1], %2, 0x989680;\n\t"
                "selp.b32 %0, 1, 0, p;\n\t}"
                : "=r"(done) : "r"(mb), "r"(0u) : "memory");
        }
    }

    if (!live) return;

    const float wr9 = cw[ 9], wr10 = cw[10], wr11 = cw[11], br = cb[0];
    const float wg9 = cw[21], wg10 = cw[22], wg11 = cw[23], bg = cb[1];
    const float wb9 = cw[33], wb10 = cw[34], wb11 = cw[35], bb = cb[2];

    while (q < nq) {
        int qn = q + stride;
        float4 rn, gn, bn;
        if (qn < nq) {
            rn = __ldcs(gR + qn);
            gn = __ldcs(gG + qn);
            bn = __ldcs(gB + qn);
        }

        float4 or4, og4, ob4;
        const float* rr = (const float*)&r4;
        const float* gg = (const float*)&g4;
        const float* bv = (const float*)&b4;
        float* po0 = (float*)&or4;
        float* po1 = (float*)&og4;
        float* po2 = (float*)&ob4;

#pragma unroll
        for (int e = 0; e < 4; e++) {
            float r = rr[e], g = gg[e], b = bv[e];

            float crd = __saturatef(r) * 15.f;
            float cgd = __saturatef(g) * 15.f;
            float cbd = __saturatef(b) * 15.f;
            int ir = (int)crd; ir = ir > 14 ? 14 : ir;
            int ig = (int)cgd; ig = ig > 14 ? 14 : ig;
            int ib = (int)cbd; ib = ib > 14 ? 14 : ib;
            __half2 fr2 = __float2half2_rn(crd - (float)ir);
            __half2 fg2 = __float2half2_rn(cgd - (float)ig);
            __half2 fb2 = __float2half2_rn(cbd - (float)ib);

            int base = ir * 256 + ig * 16 + ib;

            uint4 e00 = sg[base];
            uint4 e01 = sg[base +  16];
            uint4 e10 = sg[base + 256];
            uint4 e11 = sg[base + 272];

            H2P c00 = lerp_b(e00, fb2);
            H2P c01 = lerp_b(e01, fb2);
            H2P c10 = lerp_b(e10, fb2);
            H2P c11 = lerp_b(e11, fb2);
            H2P c0  = lerp_p(c00, c01, fg2);
            H2P c1  = lerp_p(c10, c11, fg2);
            H2P cc  = lerp_p(c0, c1, fr2);

            float2 f01 = __half22float2(cc.a);
            float  f2  = __low2float(cc.c);

            po0[e] = fmaf(wr11, b, fmaf(wr10, g, fmaf(wr9, r, f01.x + br)));
            po1[e] = fmaf(wg11, b, fmaf(wg10, g, fmaf(wg9, r, f01.y + bg)));
            po2[e] = fmaf(wb11, b, fmaf(wb10, g, fmaf(wb9, r, f2    + bb)));
        }

        __stcs(oR + q, or4);
        __stcs(oG + q, og4);
        __stcs(oB + q, ob4);

        q = qn;
        r4 = rn; g4 = gn; b4 = bn;
    }
}

// ---------------------------------------------------------------------------
// Launch
// ---------------------------------------------------------------------------
extern "C" void kernel_launch(void* const* d_in, const int* in_sizes, int n_in,
                              void* d_out, int out_size) {
    const float* grid  = (const float*)d_in[0];   // (4,9,16,16,16)
    const float* guide = (const float*)d_in[1];   // (4,3,1024,1024)
    const float* cw    = (const float*)d_in[2];   // (3,12)
    const float* cb    = (const float*)d_in[3];   // (3,)
    float* out = (float*)d_out;                   // (4,3,1024,1024)

    cudaFuncSetAttribute(slice_conv_kernel,
                         cudaFuncAttributeMaxDynamicSharedMemorySize, 65536);

    project_grid_kernel<<<(NB * DCELLS + 255) / 256, 256>>>(grid, cw);

    dim3 blocks(74, NB);   // 296 CTAs = 148 SMs x 2 CTAs/SM (64KB smem each)
    slice_conv_kernel<<<blocks, 512, 65536>>>(guide, cw, cb, out);
}